// round 11
// baseline (speedup 1.0000x reference)
#include <cuda_runtime.h>
#include <math.h>

#define T_LEN  2000
#define FC     514            // 257 * 2
#define NSER   8224           // 16 * 514
#define NPAIRS (NSER / 2)     // 4112 float2 series-pairs
#define FC2    (FC / 2)       // 257 pairs per row
#define CH     40             // number of time chunks
#define LCH    50             // chunk length (CH*LCH == T_LEN)
#define NBX    17             // ceil(NPAIRS / 256)

// Per-t constants: (w, a = 1-w, b = w*a, bP = b * Ppre_u).
__device__ float4 g_c4[T_LEN];
// Per-chunk constants: (P, gamma).
__device__ float2 g_ck[CH];
// Per (chunk, series) scratch.
__device__ float g_q [CH * NSER];
__device__ float g_al[CH * NSER];
__device__ float g_be[CH * NSER];
__device__ float g_v2[CH * NSER];
__device__ float g_s [CH * NSER];
// Completion counters per x-slice; re-zeroed by coef_kernel every launch.
__device__ int g_cnt[NBX];

// Small-exponent binary power: e <= 63 -> at most 6 iterations.
__device__ __forceinline__ double dpow(double b, int e) {
    double r = 1.0, p = b;
    while (e) { if (e & 1) r *= p; p *= p; e >>= 1; }
    return r;
}

// Constants kernel: short FP64 chains, one block per SM (R10-proven fast).
// Also resets the combine counters for graph replay.
__global__ void coef_kernel() {
    int t = blockIdx.x * 32 + threadIdx.x;
    if (blockIdx.x == 0 && threadIdx.x < NBX) g_cnt[threadIdx.x] = 0;
    if (t >= T_LEN) return;
    const double b  = (double)0.99f;
    const double c1 = (double)(1.0f - 0.99f);  // exact (Sterbenz)
    int u  = t % LCH;
    int c  = t / LCH;
    double bL  = dpow(b, LCH);
    double bt0 = dpow(bL, c);          // beta^{t0}
    double bu  = dpow(b, u);           // beta^{u}
    double bt  = bu * bt0;             // beta^{t}
    double bt1 = bt * b;               // beta^{t+1}

    double w  = c1 / (1.0 - bt1);      // w_0 == 1 exactly
    double a  = 1.0 - w;
    double bb = w * a;
    double Ppre = (u == 0) ? 1.0 : bu * (1.0 - bt0) / (1.0 - bt);
    g_c4[t] = make_float4((float)w, (float)a, (float)bb, (float)(bb * Ppre));

    if (u == 0) {
        double bt0L  = bt0 * bL;       // beta^{t0+L}
        double ratio = (1.0 - bt0) / (1.0 - bt0L);
        double P     = bL * ratio;     // 0 for chunk 0
        double ga    = (c == 0) ? 0.0
                     : (bL * (1.0 - bt0) * (1.0 - ratio)) / ((1.0 - bt0L) * bt0);
        g_ck[c] = make_float2((float)P, (float)ga);
    }
}

// Kernel 2: pass1 + combine tail.
// Publish pattern: stores -> __syncthreads -> thread0 atom.add.acq_rel.
// (R9's bug was a block-wide gpu-scope __threadfence here; one acq_rel
// atomic after syncthreads is sufficient and ~free.)
__global__ __launch_bounds__(256)
void pass1_kernel(const float* __restrict__ in) {
    __shared__ int sflag;
    int c  = blockIdx.y;
    int pr = blockIdx.x * 256 + threadIdx.x;
    bool act = (pr < NPAIRS);
    const float4* cf = g_c4 + c * LCH;

    if (act) {
        int n  = pr / FC2;
        int fp = pr - n * FC2;
        const float2* xp = (const float2*)in
                         + ((size_t)n * T_LEN + (size_t)c * LCH) * FC2 + fp;
        float Q0 = 0.f, Q1 = 0.f, al0 = 0.f, al1 = 0.f, be0 = 0.f, be1 = 0.f;
#pragma unroll 10
        for (int u = 0; u < LCH; u++) {
            float4 k = __ldg(cf + u);            // (w, a, b, bP)
            float2 x = __ldg(xp + (size_t)u * FC2);
            float u0 = x.x - Q0;
            float u1 = x.y - Q1;
            Q0 = fmaf(k.x, u0, Q0);
            Q1 = fmaf(k.x, u1, Q1);
            al0 = fmaf(k.y, al0, (k.z * u0) * u0);
            al1 = fmaf(k.y, al1, (k.z * u1) * u1);
            be0 = fmaf(k.y, be0, k.w * u0);
            be1 = fmaf(k.y, be1, k.w * u1);
        }
        int idx = c * NSER + pr * 2;
        *(float2*)&g_q [idx] = make_float2(Q0, Q1);
        *(float2*)&g_al[idx] = make_float2(al0, al1);
        *(float2*)&g_be[idx] = make_float2(be0, be1);
    }

    // Arrive: one acq_rel atomic per block publishes the block's stores
    // (syncthreads gives intra-block happens-before into thread 0).
    __syncthreads();
    if (threadIdx.x == 0) {
        int old;
        asm volatile("atom.add.acq_rel.gpu.global.s32 %0, [%1], 1;"
                     : "=r"(old) : "l"(&g_cnt[blockIdx.x]) : "memory");
        sflag = (old == CH - 1);
    }
    __syncthreads();
    if (!sflag) return;

    // Last-arriving block of this x-slice runs the combine for its pairs.
    if (act) {
        float v20 = 0.f, v21 = 0.f, S0 = 0.f, S1 = 0.f;
#pragma unroll 8
        for (int k = 0; k < CH; k++) {
            int idx = k * NSER + pr * 2;
            float2 pg = __ldg(&g_ck[k]);         // (P, gamma)
            float2 q  = __ldcg((const float2*)&g_q [idx]);
            float2 al = __ldcg((const float2*)&g_al[idx]);
            float2 be = __ldcg((const float2*)&g_be[idx]);
            *(float2*)&g_v2[idx] = make_float2(v20, v21);
            *(float2*)&g_s [idx] = make_float2(S0, S1);
            // S' = P*S + al + v2*(gamma*v2 - 2*be);  v2' = P*v2 + Q
            float c0 = fmaf(pg.y, v20, -2.0f * be.x);
            float c1 = fmaf(pg.y, v21, -2.0f * be.y);
            S0 = fmaf(pg.x, S0, fmaf(v20, c0, al.x));
            S1 = fmaf(pg.x, S1, fmaf(v21, c1, al.y));
            v20 = fmaf(pg.x, v20, q.x);
            v21 = fmaf(pg.x, v21, q.y);
        }
    }
}

// Kernel 3: pass2 — replay each chunk with exact start state, emit outputs.
__global__ __launch_bounds__(256)
void pass2_kernel(const float* __restrict__ in, float* __restrict__ out) {
    int pr = blockIdx.x * 256 + threadIdx.x;
    int c  = blockIdx.y;
    if (pr >= NPAIRS) return;
    int n  = pr / FC2;
    int fp = pr - n * FC2;
    size_t base = ((size_t)n * T_LEN + (size_t)c * LCH) * FC2 + fp;
    const float2* xp = (const float2*)in  + base;
    float2*       yp = (float2*)out + base;
    const float4* cf = g_c4 + c * LCH;

    int idx = c * NSER + pr * 2;
    float2 v2 = __ldg((const float2*)&g_v2[idx]);
    float2 S  = __ldg((const float2*)&g_s [idx]);
    float v20 = v2.x, v21 = v2.y, S0 = S.x, S1 = S.y;

#pragma unroll 10
    for (int u = 0; u < LCH; u++) {
        float4 k = __ldg(cf + u);                // (w, a, b, -)
        float2 x = __ldg(xp + (size_t)u * FC2);
        float d0 = x.x - v20;
        float d1 = x.y - v21;
        v20 = fmaf(k.x, d0, v20);
        v21 = fmaf(k.x, d1, v21);
        S0 = fmaf(k.y, S0, (k.z * d0) * d0);
        S1 = fmaf(k.y, S1, (k.z * d1) * d1);
        float r0 = rsqrtf(fmaxf(S0, 0.0f) + 1e-5f);
        float r1 = rsqrtf(fmaxf(S1, 0.0f) + 1e-5f);
        float2 y;
        y.x = (k.y * d0) * r0;
        y.y = (k.y * d1) * r1;
        __stcs(yp + (size_t)u * FC2, y);
    }
}

extern "C" void kernel_launch(void* const* d_in, const int* in_sizes, int n_in,
                              void* d_out, int out_size) {
    const float* s = (const float*)d_in[0];
    float* out = (float*)d_out;
    coef_kernel<<<63, 32>>>();                   // short-chain FP64, 1 blk/SM
    dim3 grid(NBX, CH);                          // (17, 40)
    pass1_kernel<<<grid, 256>>>(s);
    pass2_kernel<<<grid, 256>>>(s, out);
}

// round 12
// speedup vs baseline: 1.2781x; 1.2781x over previous
#include <cuda_runtime.h>
#include <math.h>

#define T_LEN  2000
#define FC     514            // 257 * 2
#define NSER   8224           // 16 * 514
#define NPAIRS (NSER / 2)     // 4112 float2 series-pairs
#define FC2    (FC / 2)       // 257 pairs per row
#define CH     40             // number of time chunks
#define LCH    50             // chunk length (CH*LCH == T_LEN)
#define NBX    17             // ceil(NPAIRS / 256)

// All data-independent constants, computed on the HOST (FP64 on-device cost
// us 5 rounds; these are pure functions of beta). 32320 bytes < 64KB constant.
struct CoefTab {
    float4 c4[T_LEN];   // per-t: (w, a = 1-w, b = w*a, bP = b * Ppre_u)
    float2 ck[CH];      // per-chunk: (P, gamma)
};
__constant__ CoefTab g_ct;

// Per (chunk, series) scratch.
__device__ float g_q [CH * NSER];
__device__ float g_al[CH * NSER];
__device__ float g_be[CH * NSER];
__device__ float g_v2[CH * NSER];
__device__ float g_s [CH * NSER];
// Completion counters per x-slice. Zero-initialized; the combiner block
// re-zeroes its own counter at the end -> graph-replay deterministic.
__device__ int g_cnt[NBX];

// Kernel 1: pass1 (chunk-local transfer coeffs) + last-block combine tail.
__global__ __launch_bounds__(256)
void pass1_kernel(const float* __restrict__ in) {
    __shared__ int sflag;
    int c  = blockIdx.y;
    int pr = blockIdx.x * 256 + threadIdx.x;
    bool act = (pr < NPAIRS);
    const float4* cf = g_ct.c4 + c * LCH;

    if (act) {
        int n  = pr / FC2;
        int fp = pr - n * FC2;
        const float2* xp = (const float2*)in
                         + ((size_t)n * T_LEN + (size_t)c * LCH) * FC2 + fp;
        float Q0 = 0.f, Q1 = 0.f, al0 = 0.f, al1 = 0.f, be0 = 0.f, be1 = 0.f;
#pragma unroll 10
        for (int u = 0; u < LCH; u++) {
            float4 k = cf[u];                    // constant cache broadcast
            float2 x = __ldg(xp + (size_t)u * FC2);
            float u0 = x.x - Q0;
            float u1 = x.y - Q1;
            Q0 = fmaf(k.x, u0, Q0);
            Q1 = fmaf(k.x, u1, Q1);
            al0 = fmaf(k.y, al0, (k.z * u0) * u0);
            al1 = fmaf(k.y, al1, (k.z * u1) * u1);
            be0 = fmaf(k.y, be0, k.w * u0);
            be1 = fmaf(k.y, be1, k.w * u1);
        }
        int idx = c * NSER + pr * 2;
        *(float2*)&g_q [idx] = make_float2(Q0, Q1);
        *(float2*)&g_al[idx] = make_float2(al0, al1);
        *(float2*)&g_be[idx] = make_float2(be0, be1);
    }

    // Arrive: one acq_rel atomic per block publishes the block's stores.
    __syncthreads();
    if (threadIdx.x == 0) {
        int old;
        asm volatile("atom.add.acq_rel.gpu.global.s32 %0, [%1], 1;"
                     : "=r"(old) : "l"(&g_cnt[blockIdx.x]) : "memory");
        sflag = (old == CH - 1);
    }
    __syncthreads();
    if (!sflag) return;

    // Last-arriving block of this x-slice runs the combine for its pairs.
    if (act) {
        float v20 = 0.f, v21 = 0.f, S0 = 0.f, S1 = 0.f;
#pragma unroll 8
        for (int k = 0; k < CH; k++) {
            int idx = k * NSER + pr * 2;
            float2 pg = g_ct.ck[k];              // (P, gamma)
            float2 q  = __ldcg((const float2*)&g_q [idx]);
            float2 al = __ldcg((const float2*)&g_al[idx]);
            float2 be = __ldcg((const float2*)&g_be[idx]);
            *(float2*)&g_v2[idx] = make_float2(v20, v21);
            *(float2*)&g_s [idx] = make_float2(S0, S1);
            // S' = P*S + al + v2*(gamma*v2 - 2*be);  v2' = P*v2 + Q
            float c0 = fmaf(pg.y, v20, -2.0f * be.x);
            float c1 = fmaf(pg.y, v21, -2.0f * be.y);
            S0 = fmaf(pg.x, S0, fmaf(v20, c0, al.x));
            S1 = fmaf(pg.x, S1, fmaf(v21, c1, al.y));
            v20 = fmaf(pg.x, v20, q.x);
            v21 = fmaf(pg.x, v21, q.y);
        }
    }
    // Self-reset for the next (graph-replayed) launch.
    if (threadIdx.x == 0) g_cnt[blockIdx.x] = 0;
}

// Kernel 2: pass2 — replay each chunk with exact start state, emit outputs.
__global__ __launch_bounds__(256)
void pass2_kernel(const float* __restrict__ in, float* __restrict__ out) {
    int pr = blockIdx.x * 256 + threadIdx.x;
    int c  = blockIdx.y;
    if (pr >= NPAIRS) return;
    int n  = pr / FC2;
    int fp = pr - n * FC2;
    size_t base = ((size_t)n * T_LEN + (size_t)c * LCH) * FC2 + fp;
    const float2* xp = (const float2*)in  + base;
    float2*       yp = (float2*)out + base;
    const float4* cf = g_ct.c4 + c * LCH;

    int idx = c * NSER + pr * 2;
    float2 v2 = __ldg((const float2*)&g_v2[idx]);
    float2 S  = __ldg((const float2*)&g_s [idx]);
    float v20 = v2.x, v21 = v2.y, S0 = S.x, S1 = S.y;

#pragma unroll 10
    for (int u = 0; u < LCH; u++) {
        float4 k = cf[u];                        // constant cache broadcast
        float2 x = __ldg(xp + (size_t)u * FC2);
        float d0 = x.x - v20;
        float d1 = x.y - v21;
        v20 = fmaf(k.x, d0, v20);
        v21 = fmaf(k.x, d1, v21);
        S0 = fmaf(k.y, S0, (k.z * d0) * d0);
        S1 = fmaf(k.y, S1, (k.z * d1) * d1);
        float r0 = rsqrtf(fmaxf(S0, 0.0f) + 1e-5f);
        float r1 = rsqrtf(fmaxf(S1, 0.0f) + 1e-5f);
        float2 y;
        y.x = (k.y * d0) * r0;
        y.y = (k.y * d1) * r1;
        __stcs(yp + (size_t)u * FC2, y);
    }
}

// Static host-side coefficient table: stays valid across graph replays.
static CoefTab h_ct;

static void fill_coefs_host() {
    const double b  = (double)0.99f;
    const double c1 = (double)(1.0f - 0.99f);   // exact (Sterbenz)
    for (int t = 0; t < T_LEN; t++) {
        int u  = t % LCH;
        int t0 = t - u;
        double bt1 = pow(b, (double)(t + 1));
        double w   = c1 / (1.0 - bt1);          // w_0 == 1 exactly
        double a   = 1.0 - w;
        double bb  = w * a;
        double Ppre = (u == 0) ? 1.0
                    : pow(b, (double)u) * (1.0 - pow(b, (double)t0))
                      / (1.0 - pow(b, (double)t));
        h_ct.c4[t] = make_float4((float)w, (float)a, (float)bb,
                                 (float)(bb * Ppre));
    }
    for (int c = 0; c < CH; c++) {
        int t0 = c * LCH;
        double ratio = (1.0 - pow(b, (double)t0))
                     / (1.0 - pow(b, (double)(t0 + LCH)));
        double P     = pow(b, (double)LCH) * ratio;   // 0 for chunk 0
        double ga    = (c == 0) ? 0.0
                     : (P / pow(b, (double)t0)) * (1.0 - ratio);
        h_ct.ck[c] = make_float2((float)P, (float)ga);
    }
}

extern "C" void kernel_launch(void* const* d_in, const int* in_sizes, int n_in,
                              void* d_out, int out_size) {
    const float* s = (const float*)d_in[0];
    float* out = (float*)d_out;
    fill_coefs_host();   // same values every call -> deterministic
    cudaMemcpyToSymbolAsync(g_ct, &h_ct, sizeof(CoefTab), 0,
                            cudaMemcpyHostToDevice);
    dim3 grid(NBX, CH);                          // (17, 40)
    pass1_kernel<<<grid, 256>>>(s);
    pass2_kernel<<<grid, 256>>>(s, out);
}